// round 11
// baseline (speedup 1.0000x reference)
#include <cuda_runtime.h>
#include <math.h>

#define NB 100
#define NPG 500
#define EPG 8000
#define NN (NB * NPG)
#define F_IN 64
#define HEADS 4
#define DH 16
#define HID 256
#define SPLIT 4
#define EG4 (EPG / 4)          // 2000 int4 edge groups per graph
#define G4S (EG4 / SPLIT)      // 500 groups per split
#define BCAP 22                // bucket cap: Poisson(4), P(>=22)~5e-11
#define QNPG 125               // nodes per adt block

// ---------------- global scratch ----------------
__device__ float g_me[NB * 64];                  // msg_emb
__device__ float g_as[NN * 4];
__device__ float g_ad[NN * 4];
__device__ float g_t[NN * 4];
__device__ float g_part[NB * SPLIT * 8 * NPG];   // SoA: [block][component][dst]

// ================= K_0: msg_emb, one warp per channel =================
__global__ void __launch_bounds__(1024)
msg_kernel(const float* __restrict__ message,
           const float* __restrict__ fc_w,
           const float* __restrict__ fc_b) {
    const int b = blockIdx.x;
    const int tid = threadIdx.x;
    const int w = tid >> 5, lane = tid & 31;

    __shared__ float ms[HID];
    if (tid < 64) {
        float4 v = ((const float4*)(message + b * HID))[tid];
        *(float4*)&ms[tid * 4] = v;
    }
    __syncthreads();

    // warp w handles channels w and w+32; lanes cover 8 k's each (coalesced 32B/lane)
#pragma unroll
    for (int cc = 0; cc < 2; cc++) {
        const int c = w + cc * 32;
        const float4* fr = (const float4*)(fc_w + c * HID);
        float4 a = fr[lane * 2];
        float4 bb = fr[lane * 2 + 1];
        float4 m0 = *(const float4*)&ms[lane * 8];
        float4 m1 = *(const float4*)&ms[lane * 8 + 4];
        float acc = a.x * m0.x + a.y * m0.y + a.z * m0.z + a.w * m0.w
                  + bb.x * m1.x + bb.y * m1.y + bb.z * m1.z + bb.w * m1.w;
#pragma unroll
        for (int o = 16; o > 0; o >>= 1) acc += __shfl_xor_sync(0xffffffffu, acc, o);
        if (lane == 0) g_me[b * 64 + c] = acc + fc_b[c];
    }
}

// ================= K_A: As/Ad/T, 4 threads per node, x direct from global =================
__global__ void __launch_bounds__(512)
adt_kernel(const float* __restrict__ x,
           const float* __restrict__ W,
           const float* __restrict__ a_src,
           const float* __restrict__ a_dst) {
    const int b = blockIdx.x >> 2;
    const int qb = blockIdx.x & 3;
    const int tid = threadIdx.x;

    __shared__ float sws[256], swd[256], swt[256], sme[64];

    if (tid < 64) sme[tid] = g_me[b * 64 + tid];
    __syncthreads();

    // folded weights (256 threads)
    if (tid < 256) {
        const int f = tid >> 2, hh = tid & 3;
        const float* wrow = W + (f * HEADS + hh) * DH;
        const float* av = a_src + hh * DH;
        const float* dv = a_dst + hh * DH;
        const float* mv = sme + hh * DH;
        float s = 0.f, d = 0.f, t = 0.f;
#pragma unroll
        for (int k = 0; k < DH; k++) {
            float wv = wrow[k];
            s += wv * av[k]; d += wv * dv[k]; t += wv * mv[k];
        }
        sws[f * 4 + hh] = s;
        swd[f * 4 + hh] = d;
        swt[f * 4 + hh] = t;
    }
    __syncthreads();

    // GEMM: thread quad per node; each thread covers 16 features (4 float4 from global)
    const int n = tid >> 2;      // 0..127
    const int q = tid & 3;       // feature quarter
    if (n < QNPG) {
        const int gn = b * NPG + qb * QNPG + n;
        const float4* xr = ((const float4*)x) + (size_t)gn * 16 + q * 4;
        float4 xv0 = xr[0], xv1 = xr[1], xv2 = xr[2], xv3 = xr[3];
        const float4* ws4 = (const float4*)sws;
        const float4* wd4 = (const float4*)swd;
        const float4* wt4 = (const float4*)swt;
        float4 as = {0,0,0,0}, ad = {0,0,0,0}, tt = {0,0,0,0};
#pragma unroll
        for (int i = 0; i < 4; i++) {
            float4 xv = (i == 0) ? xv0 : (i == 1) ? xv1 : (i == 2) ? xv2 : xv3;
#pragma unroll
            for (int j = 0; j < 4; j++) {
                float xf = (j == 0) ? xv.x : (j == 1) ? xv.y : (j == 2) ? xv.z : xv.w;
                const int fi = q * 16 + i * 4 + j;
                float4 w1 = ws4[fi];
                float4 w2 = wd4[fi];
                float4 w3 = wt4[fi];
                as.x += xf * w1.x; as.y += xf * w1.y; as.z += xf * w1.z; as.w += xf * w1.w;
                ad.x += xf * w2.x; ad.y += xf * w2.y; ad.z += xf * w2.z; ad.w += xf * w2.w;
                tt.x += xf * w3.x; tt.y += xf * w3.y; tt.z += xf * w3.z; tt.w += xf * w3.w;
            }
        }
        // reduce over the 4-lane quad
#pragma unroll
        for (int o = 1; o <= 2; o <<= 1) {
            as.x += __shfl_xor_sync(0xffffffffu, as.x, o);
            as.y += __shfl_xor_sync(0xffffffffu, as.y, o);
            as.z += __shfl_xor_sync(0xffffffffu, as.z, o);
            as.w += __shfl_xor_sync(0xffffffffu, as.w, o);
            ad.x += __shfl_xor_sync(0xffffffffu, ad.x, o);
            ad.y += __shfl_xor_sync(0xffffffffu, ad.y, o);
            ad.z += __shfl_xor_sync(0xffffffffu, ad.z, o);
            ad.w += __shfl_xor_sync(0xffffffffu, ad.w, o);
            tt.x += __shfl_xor_sync(0xffffffffu, tt.x, o);
            tt.y += __shfl_xor_sync(0xffffffffu, tt.y, o);
            tt.z += __shfl_xor_sync(0xffffffffu, tt.z, o);
            tt.w += __shfl_xor_sync(0xffffffffu, tt.w, o);
        }
        if (q == 0) {
            ((float4*)g_as)[gn] = as;
            ((float4*)g_ad)[gn] = ad;
            ((float4*)g_t)[gn] = tt;
        }
    }
}

// ================= K_B: scatter split edges + partial gather =================
__global__ void __launch_bounds__(256)
part_kernel(const int* __restrict__ esrc,
            const int* __restrict__ edst) {
    const int b = blockIdx.x >> 2;
    const int q = blockIdx.x & 3;
    const int nbase = b * NPG;
    const int tid = threadIdx.x;

    __shared__ float sAs[NPG * 4];
    __shared__ float sAd[NPG * 4];
    __shared__ float sT[NPG * 4];
    __shared__ int cur[NPG];
    __shared__ unsigned short buck[NPG * BCAP];

    if (tid < 128) {
        for (int i = tid; i < NPG; i += 128)
            ((float4*)sAs)[i] = ((const float4*)g_as)[nbase + i];
        for (int i = tid; i < NPG; i += 128)
            ((float4*)sAd)[i] = ((const float4*)g_ad)[nbase + i];
        for (int i = tid; i < NPG; i += 128)
            ((float4*)sT)[i] = ((const float4*)g_t)[nbase + i];
    } else {
        const int lt = tid - 128;
        for (int i = lt; i < NPG; i += 128) cur[i] = 0;
        asm volatile("bar.sync 2, 128;" ::: "memory");
        const int e0 = q * G4S;
        for (int i = e0 + lt; i < e0 + G4S; i += 128) {
            int4 s4 = ((const int4*)(esrc + b * EPG))[i];
            int4 d4 = ((const int4*)(edst + b * EPG))[i];
            int d0 = d4.x - nbase, d1 = d4.y - nbase,
                d2 = d4.z - nbase, d3 = d4.w - nbase;
            int p0 = atomicAdd(&cur[d0], 1);
            if (p0 < BCAP) buck[d0 * BCAP + p0] = (unsigned short)(s4.x - nbase);
            int p1 = atomicAdd(&cur[d1], 1);
            if (p1 < BCAP) buck[d1 * BCAP + p1] = (unsigned short)(s4.y - nbase);
            int p2 = atomicAdd(&cur[d2], 1);
            if (p2 < BCAP) buck[d2 * BCAP + p2] = (unsigned short)(s4.z - nbase);
            int p3 = atomicAdd(&cur[d3], 1);
            if (p3 < BCAP) buck[d3 * BCAP + p3] = (unsigned short)(s4.w - nbase);
        }
    }
    __syncthreads();

    // ---- partial gather: 8 components, SoA coalesced stores ----
    float* gp = g_part + (size_t)blockIdx.x * 8 * NPG;
    for (int d = tid; d < NPG; d += 256) {
        int n = cur[d]; n = (n < BCAP) ? n : BCAP;
        const float4 ad4 = *(const float4*)&sAd[d * 4];
        const unsigned short* bk = buck + d * BCAP;
        float den0 = 0.f, den1 = 0.f, den2 = 0.f, den3 = 0.f;
        float ac0 = 0.f, ac1 = 0.f, ac2 = 0.f, ac3 = 0.f;
        for (int j = 0; j < n; j++) {
            const int s = bk[j];
            const float4 as4 = *(const float4*)&sAs[s * 4];
            const float4 t4 = *(const float4*)&sT[s * 4];
            float e0 = as4.x + ad4.x; e0 = (e0 > 0.f) ? e0 : 0.2f * e0;
            float e1 = as4.y + ad4.y; e1 = (e1 > 0.f) ? e1 : 0.2f * e1;
            float e2 = as4.z + ad4.z; e2 = (e2 > 0.f) ? e2 : 0.2f * e2;
            float e3 = as4.w + ad4.w; e3 = (e3 > 0.f) ? e3 : 0.2f * e3;
            float x0 = __expf(e0), x1 = __expf(e1), x2 = __expf(e2), x3 = __expf(e3);
            den0 += x0; den1 += x1; den2 += x2; den3 += x3;
            ac0 += x0 * t4.x; ac1 += x1 * t4.y; ac2 += x2 * t4.z; ac3 += x3 * t4.w;
        }
        gp[0 * NPG + d] = den0;
        gp[1 * NPG + d] = den1;
        gp[2 * NPG + d] = den2;
        gp[3 * NPG + d] = den3;
        gp[4 * NPG + d] = ac0;
        gp[5 * NPG + d] = ac1;
        gp[6 * NPG + d] = ac2;
        gp[7 * NPG + d] = ac3;
    }
}

// ================= K_C: combine splits + bconst + log_softmax =================
__global__ void __launch_bounds__(512)
combine_kernel(const float* __restrict__ bias,
               float* __restrict__ out) {
    const int b = blockIdx.x;
    const int tid = threadIdx.x;

    // bconst = bias . me (warps 0-1)
    __shared__ float sbc[2];
    if (tid < 64) {
        float p = bias[tid] * g_me[b * 64 + tid];
#pragma unroll
        for (int o = 16; o > 0; o >>= 1) p += __shfl_xor_sync(0xffffffffu, p, o);
        if ((tid & 31) == 0) sbc[tid >> 5] = p;
    }
    __syncthreads();
    const float bc = sbc[0] + sbc[1];

    float v = -INFINITY;
    if (tid < NPG) {
        float den0 = 0.f, den1 = 0.f, den2 = 0.f, den3 = 0.f;
        float ac0 = 0.f, ac1 = 0.f, ac2 = 0.f, ac3 = 0.f;
#pragma unroll
        for (int s = 0; s < SPLIT; s++) {
            const float* gp = g_part + (size_t)(b * SPLIT + s) * 8 * NPG + tid;
            den0 += gp[0 * NPG]; den1 += gp[1 * NPG];
            den2 += gp[2 * NPG]; den3 += gp[3 * NPG];
            ac0 += gp[4 * NPG]; ac1 += gp[5 * NPG];
            ac2 += gp[6 * NPG]; ac3 += gp[7 * NPG];
        }
        float r0 = (den0 > 0.f) ? __fdividef(ac0, den0) : 0.f;
        float r1 = (den1 > 0.f) ? __fdividef(ac1, den1) : 0.f;
        float r2 = (den2 > 0.f) ? __fdividef(ac2, den2) : 0.f;
        float r3 = (den3 > 0.f) ? __fdividef(ac3, den3) : 0.f;
        v = r0 + r1 + r2 + r3 + bc;
    }

    __shared__ float lred[16];
    float m = v;
#pragma unroll
    for (int o = 16; o > 0; o >>= 1) m = fmaxf(m, __shfl_xor_sync(0xffffffffu, m, o));
    if ((tid & 31) == 0) lred[tid >> 5] = m;
    __syncthreads();
    if (tid < 32) {
        float t = (tid < 16) ? lred[tid] : -INFINITY;
#pragma unroll
        for (int o = 8; o > 0; o >>= 1) t = fmaxf(t, __shfl_xor_sync(0xffffffffu, t, o));
        if (tid == 0) lred[0] = t;
    }
    __syncthreads();
    m = lred[0];
    __syncthreads();
    float p = (tid < NPG) ? __expf(v - m) : 0.0f;
    float s = p;
#pragma unroll
    for (int o = 16; o > 0; o >>= 1) s += __shfl_xor_sync(0xffffffffu, s, o);
    if ((tid & 31) == 0) lred[tid >> 5] = s;
    __syncthreads();
    if (tid < 32) {
        float t = (tid < 16) ? lred[tid] : 0.0f;
#pragma unroll
        for (int o = 8; o > 0; o >>= 1) t += __shfl_xor_sync(0xffffffffu, t, o);
        if (tid == 0) lred[0] = t;
    }
    __syncthreads();
    const float lse = m + logf(lred[0]);
    if (tid < NPG) out[b * NPG + tid] = v - lse;
}

// ---------------- Launch ----------------
extern "C" void kernel_launch(void* const* d_in, const int* in_sizes, int n_in,
                              void* d_out, int out_size) {
    const float* message = (const float*)d_in[0];
    const float* x       = (const float*)d_in[1];
    const int*   esrc    = (const int*)d_in[2];
    const int*   edst    = (const int*)d_in[3];
    const float* W       = (const float*)d_in[4];
    const float* a_src   = (const float*)d_in[5];
    const float* a_dst   = (const float*)d_in[6];
    const float* bias    = (const float*)d_in[7];
    const float* fc_w    = (const float*)d_in[8];
    const float* fc_b    = (const float*)d_in[9];
    float* out = (float*)d_out;

    msg_kernel<<<NB, 1024>>>(message, fc_w, fc_b);
    adt_kernel<<<NB * 4, 512>>>(x, W, a_src, a_dst);
    part_kernel<<<NB * SPLIT, 256>>>(esrc, edst);
    combine_kernel<<<NB, 512>>>(bias, out);
}

// round 13
// speedup vs baseline: 2.5069x; 2.5069x over previous
#include <cuda_runtime.h>
#include <cstdint>
#include <math.h>

#define NB 100
#define NPG 500
#define EPG 8000
#define F_IN 64
#define HEADS 4
#define DH 16
#define EMB 64
#define HID 256
#define NTH 512
#define BCAP 50
#define ESPLIT4 1500   // int4-edge groups: scatter warps take [0,1500), GEMM warps join [1500,2000)

// ---------------- smem layout (float words) ----------------
#define OFF_WS 0          // ws4[64*4] folded W@a_src, float4 over heads per feature
#define OFF_WD 256        // wd4[64*4]
#define OFF_WT 512        // wt4[64*4]
#define OFF_ME 768        // me[64]
#define OFF_BC 832        // bconst
#define OFF_AS 836        // A_s4f[2000]
#define OFF_AD 2836       // A_d4f[2000]
#define OFF_T  4836       // T4f[2000]
#define OFF_CUR 6836      // cur[500] int
#define OFF_BUCK 7336     // buck ushort[500*50] = 12500 words
#define OFF_XS 19836      // xs[500*68] = 34000 words
#define SMEM_WORDS (OFF_XS + NPG * 68)
#define SMEM_BYTES (SMEM_WORDS * 4)   // 215,344 B

extern __shared__ float smem[];

__device__ __forceinline__ uint32_t smem_u32(const void* p) {
    uint32_t a;
    asm("{ .reg .u64 t; cvta.to.shared.u64 t, %1; cvt.u32.u64 %0, t; }"
        : "=r"(a) : "l"(p));
    return a;
}
__device__ __forceinline__ void cp16(uint32_t dst, const void* src) {
    asm volatile("cp.async.cg.shared.global [%0], [%1], 16;" :: "r"(dst), "l"(src));
}

__global__ void __launch_bounds__(NTH, 1)
fused_kernel(const float* __restrict__ message,
             const float* __restrict__ x,
             const int* __restrict__ esrc,
             const int* __restrict__ edst,
             const float* __restrict__ W,
             const float* __restrict__ a_src,
             const float* __restrict__ a_dst,
             const float* __restrict__ bias,
             const float* __restrict__ fc_w,
             const float* __restrict__ fc_b,
             float* __restrict__ out) {
    const int b = blockIdx.x;
    const int nbase = b * NPG;
    const int ebase = b * EPG;
    const int tid = threadIdx.x;

    float* me = smem + OFF_ME;
    float* A_s4f = smem + OFF_AS;
    float* A_d4f = smem + OFF_AD;
    float* T4f = smem + OFF_T;
    int* cur = (int*)(smem + OFF_CUR);
    unsigned short* buck = (unsigned short*)(smem + OFF_BUCK);
    float* xs = smem + OFF_XS;

    if (tid < 256) {
        // ================= GEMM side: warps 0-7 =================
        // ---- kick off x staging via cp.async: deep MLP, no reg round-trip ----
        {
            const uint32_t s0 = smem_u32(xs);
            const float4* xg = ((const float4*)x) + (size_t)nbase * 16;
#pragma unroll 8
            for (int i = tid; i < NPG * 16; i += 256) {
                int r = i >> 4, f4 = i & 15;
                cp16(s0 + (uint32_t)(r * 68 + f4 * 4) * 4, xg + i);
            }
            asm volatile("cp.async.commit_group;" ::: "memory");
        }

        // ---- Phase A: me, warp-per-channel coalesced fc_w reads ----
        {
            const int w = tid >> 5, lane = tid & 31;
            const float4* mr = (const float4*)(message + b * HID);
            float4 m0 = mr[lane * 2];
            float4 m1 = mr[lane * 2 + 1];
#pragma unroll
            for (int cc = 0; cc < 8; cc++) {
                const int c = (w << 3) | cc;
                const float4* fr = (const float4*)(fc_w + c * HID);
                float4 a = fr[lane * 2];
                float4 g = fr[lane * 2 + 1];
                float acc = a.x * m0.x + a.y * m0.y + a.z * m0.z + a.w * m0.w
                          + g.x * m1.x + g.y * m1.y + g.z * m1.z + g.w * m1.w;
#pragma unroll
                for (int o = 16; o > 0; o >>= 1) acc += __shfl_xor_sync(0xffffffffu, acc, o);
                if (lane == 0) me[c] = acc + fc_b[c];
            }
        }
        asm volatile("bar.sync 1, 256;" ::: "memory");

        // ---- Phase B: folded weights, float4-over-heads per feature ----
        {
            const int f = tid >> 2, hh = tid & 3;
            const float* wrow = W + (f * HEADS + hh) * DH;
            const float* av = a_src + hh * DH;
            const float* dv = a_dst + hh * DH;
            const float* mv = me + hh * DH;
            float s = 0.f, d = 0.f, t = 0.f;
#pragma unroll
            for (int k = 0; k < DH; k++) {
                float wv = wrow[k];
                s += wv * av[k]; d += wv * dv[k]; t += wv * mv[k];
            }
            smem[OFF_WS + f * 4 + hh] = s;
            smem[OFF_WD + f * 4 + hh] = d;
            smem[OFF_WT + f * 4 + hh] = t;
        }
        // bconst = bias . me (warp 0)
        if (tid < 32) {
            float v = bias[tid] * me[tid] + bias[tid + 32] * me[tid + 32];
#pragma unroll
            for (int o = 16; o > 0; o >>= 1) v += __shfl_xor_sync(0xffffffffu, v, o);
            if (tid == 0) smem[OFF_BC] = v;
        }
        // x staging must be complete (and visible after the barrier)
        asm volatile("cp.async.wait_group 0;" ::: "memory");
        asm volatile("bar.sync 1, 256;" ::: "memory");

        // ---- Phase C: broadcast-weight GEMM. Thread owns 2 nodes, all heads. ----
        {
            const int n0 = tid;           // 0..255
            int n1 = tid + 256;           // 256..511
            const bool v1 = (n1 < NPG);
            if (!v1) n1 = NPG - 1;
            const float* xr0 = xs + n0 * 68;
            const float* xr1 = xs + n1 * 68;
            const float4* ws4 = (const float4*)(smem + OFF_WS);
            const float4* wd4 = (const float4*)(smem + OFF_WD);
            const float4* wt4 = (const float4*)(smem + OFF_WT);
            float4 as0 = {0,0,0,0}, ad0 = {0,0,0,0}, tt0 = {0,0,0,0};
            float4 as1 = {0,0,0,0}, ad1 = {0,0,0,0}, tt1 = {0,0,0,0};
#pragma unroll
            for (int f4 = 0; f4 < 16; f4++) {
                float4 x0 = *(const float4*)(xr0 + f4 * 4);
                float4 x1 = *(const float4*)(xr1 + f4 * 4);
#pragma unroll
                for (int j = 0; j < 4; j++) {
                    float xf0 = (j == 0) ? x0.x : (j == 1) ? x0.y : (j == 2) ? x0.z : x0.w;
                    float xf1 = (j == 0) ? x1.x : (j == 1) ? x1.y : (j == 2) ? x1.z : x1.w;
                    float4 w1 = ws4[f4 * 4 + j];   // broadcast (same addr all lanes)
                    float4 w2 = wd4[f4 * 4 + j];
                    float4 w3 = wt4[f4 * 4 + j];
                    as0.x += xf0 * w1.x; as0.y += xf0 * w1.y; as0.z += xf0 * w1.z; as0.w += xf0 * w1.w;
                    ad0.x += xf0 * w2.x; ad0.y += xf0 * w2.y; ad0.z += xf0 * w2.z; ad0.w += xf0 * w2.w;
                    tt0.x += xf0 * w3.x; tt0.y += xf0 * w3.y; tt0.z += xf0 * w3.z; tt0.w += xf0 * w3.w;
                    as1.x += xf1 * w1.x; as1.y += xf1 * w1.y; as1.z += xf1 * w1.z; as1.w += xf1 * w1.w;
                    ad1.x += xf1 * w2.x; ad1.y += xf1 * w2.y; ad1.z += xf1 * w2.z; ad1.w += xf1 * w2.w;
                    tt1.x += xf1 * w3.x; tt1.y += xf1 * w3.y; tt1.z += xf1 * w3.z; tt1.w += xf1 * w3.w;
                }
            }
            *(float4*)&A_s4f[n0 * 4] = as0;
            *(float4*)&A_d4f[n0 * 4] = ad0;
            *(float4*)&T4f[n0 * 4] = tt0;
            if (v1) {
                *(float4*)&A_s4f[n1 * 4] = as1;
                *(float4*)&A_d4f[n1 * 4] = ad1;
                *(float4*)&T4f[n1 * 4] = tt1;
            }
        }

        // ---- GEMM warps join scatter on edge tail [ESPLIT4, 2000) ----
        for (int i = ESPLIT4 + tid; i < EPG / 4; i += 256) {
            int4 s4 = ((const int4*)(esrc + ebase))[i];
            int4 d4 = ((const int4*)(edst + ebase))[i];
            int d0 = d4.x - nbase, d1 = d4.y - nbase,
                d2 = d4.z - nbase, d3 = d4.w - nbase;
            int p0 = atomicAdd(&cur[d0], 1);
            if (p0 < BCAP) buck[d0 * BCAP + p0] = (unsigned short)(s4.x - nbase);
            int p1 = atomicAdd(&cur[d1], 1);
            if (p1 < BCAP) buck[d1 * BCAP + p1] = (unsigned short)(s4.y - nbase);
            int p2 = atomicAdd(&cur[d2], 1);
            if (p2 < BCAP) buck[d2 * BCAP + p2] = (unsigned short)(s4.z - nbase);
            int p3 = atomicAdd(&cur[d3], 1);
            if (p3 < BCAP) buck[d3 * BCAP + p3] = (unsigned short)(s4.w - nbase);
        }
    } else {
        // ================= Scatter side: warps 8-15, edges [0, ESPLIT4) =================
        const int lt = tid - 256;
        for (int i = lt; i < NPG; i += 256) cur[i] = 0;
        asm volatile("bar.sync 2, 256;" ::: "memory");
        for (int i = lt; i < ESPLIT4; i += 256) {
            int4 s4 = ((const int4*)(esrc + ebase))[i];
            int4 d4 = ((const int4*)(edst + ebase))[i];
            int d0 = d4.x - nbase, d1 = d4.y - nbase,
                d2 = d4.z - nbase, d3 = d4.w - nbase;
            int p0 = atomicAdd(&cur[d0], 1);
            if (p0 < BCAP) buck[d0 * BCAP + p0] = (unsigned short)(s4.x - nbase);
            int p1 = atomicAdd(&cur[d1], 1);
            if (p1 < BCAP) buck[d1 * BCAP + p1] = (unsigned short)(s4.y - nbase);
            int p2 = atomicAdd(&cur[d2], 1);
            if (p2 < BCAP) buck[d2 * BCAP + p2] = (unsigned short)(s4.z - nbase);
            int p3 = atomicAdd(&cur[d3], 1);
            if (p3 < BCAP) buck[d3 * BCAP + p3] = (unsigned short)(s4.w - nbase);
        }
    }
    __syncthreads();

    // ---- Gather: one thread per dst, 4 heads vectorized ----
    float v = -INFINITY;
    if (tid < NPG) {
        const int d = tid;
        int n = cur[d]; n = (n < BCAP) ? n : BCAP;
        const float4 ad4 = *(const float4*)&A_d4f[d * 4];
        const unsigned short* bk = buck + d * BCAP;
        float den0 = 0.f, den1 = 0.f, den2 = 0.f, den3 = 0.f;
        float ac0 = 0.f, ac1 = 0.f, ac2 = 0.f, ac3 = 0.f;
        for (int j = 0; j < n; j++) {
            const int s = bk[j];
            const float4 as4 = *(const float4*)&A_s4f[s * 4];
            const float4 t4 = *(const float4*)&T4f[s * 4];
            float e0 = as4.x + ad4.x; e0 = (e0 > 0.f) ? e0 : 0.2f * e0;
            float e1 = as4.y + ad4.y; e1 = (e1 > 0.f) ? e1 : 0.2f * e1;
            float e2 = as4.z + ad4.z; e2 = (e2 > 0.f) ? e2 : 0.2f * e2;
            float e3 = as4.w + ad4.w; e3 = (e3 > 0.f) ? e3 : 0.2f * e3;
            float x0 = __expf(e0), x1 = __expf(e1), x2 = __expf(e2), x3 = __expf(e3);
            den0 += x0; den1 += x1; den2 += x2; den3 += x3;
            ac0 += x0 * t4.x; ac1 += x1 * t4.y; ac2 += x2 * t4.z; ac3 += x3 * t4.w;
        }
        float r0 = (den0 > 0.f) ? __fdividef(ac0, den0) : 0.f;
        float r1 = (den1 > 0.f) ? __fdividef(ac1, den1) : 0.f;
        float r2 = (den2 > 0.f) ? __fdividef(ac2, den2) : 0.f;
        float r3 = (den3 > 0.f) ? __fdividef(ac3, den3) : 0.f;
        v = r0 + r1 + r2 + r3 + smem[OFF_BC];
    }

    // ---- log_softmax over 500 nodes ----
    __shared__ float lred[16];
    float m = v;
#pragma unroll
    for (int o = 16; o > 0; o >>= 1) m = fmaxf(m, __shfl_xor_sync(0xffffffffu, m, o));
    if ((tid & 31) == 0) lred[tid >> 5] = m;
    __syncthreads();
    if (tid < 32) {
        float t = (tid < 16) ? lred[tid] : -INFINITY;
#pragma unroll
        for (int o = 8; o > 0; o >>= 1) t = fmaxf(t, __shfl_xor_sync(0xffffffffu, t, o));
        if (tid == 0) lred[0] = t;
    }
    __syncthreads();
    m = lred[0];
    __syncthreads();
    float p = (tid < NPG) ? __expf(v - m) : 0.0f;
    float s = p;
#pragma unroll
    for (int o = 16; o > 0; o >>= 1) s += __shfl_xor_sync(0xffffffffu, s, o);
    if ((tid & 31) == 0) lred[tid >> 5] = s;
    __syncthreads();
    if (tid < 32) {
        float t = (tid < 16) ? lred[tid] : 0.0f;
#pragma unroll
        for (int o = 8; o > 0; o >>= 1) t += __shfl_xor_sync(0xffffffffu, t, o);
        if (tid == 0) lred[0] = t;
    }
    __syncthreads();
    const float lse = m + logf(lred[0]);
    if (tid < NPG) out[b * NPG + tid] = v - lse;
}

// ---------------- Launch ----------------
extern "C" void kernel_launch(void* const* d_in, const int* in_sizes, int n_in,
                              void* d_out, int out_size) {
    const float* message = (const float*)d_in[0];
    const float* x       = (const float*)d_in[1];
    const int*   esrc    = (const int*)d_in[2];
    const int*   edst    = (const int*)d_in[3];
    const float* W       = (const float*)d_in[4];
    const float* a_src   = (const float*)d_in[5];
    const float* a_dst   = (const float*)d_in[6];
    const float* bias    = (const float*)d_in[7];
    const float* fc_w    = (const float*)d_in[8];
    const float* fc_b    = (const float*)d_in[9];
    float* out = (float*)d_out;

    static int init = 0;
    if (!init) {
        cudaFuncSetAttribute(fused_kernel, cudaFuncAttributeMaxDynamicSharedMemorySize, SMEM_BYTES);
        init = 1;
    }

    fused_kernel<<<NB, NTH, SMEM_BYTES>>>(message, x, esrc, edst, W,
                                          a_src, a_dst, bias, fc_w, fc_b, out);
}